// round 6
// baseline (speedup 1.0000x reference)
#include <cuda_runtime.h>
#include <cuda_fp16.h>
#include <cstdint>

#define NB 2
#define NN 8192
#define BM 64
#define NTILES 64
#define L2E 1.4426950408889634f

// -------- scratch (device globals; no allocation allowed) --------
__device__ __align__(16) __half g_Qh[NB][NN][16];  // fp16 Q, pre-scaled by log2e (A side)
__device__ __align__(16) __half g_Kh[NB][NN][16];  // fp16 K, unscaled (B side)
__device__ __align__(16) __half g_Vh[NB][NN][32];  // fp16 V
__device__ float g_Rn[NB][NN];                     // |Q_i|^2 (fp32, unscaled)
__device__ float g_bmax[NB][256];                  // per-block max |Q|^2 (no reset needed)

// ---------------- helpers ----------------
__device__ __forceinline__ uint32_t smem_u32(const void* p) {
    uint32_t a;
    asm("{ .reg .u64 t; cvta.to.shared.u64 t, %1; cvt.u32.u64 %0, t; }" : "=r"(a) : "l"(p));
    return a;
}
__device__ __forceinline__ void ldsm4(uint32_t* r, uint32_t a) {
    asm volatile("ldmatrix.sync.aligned.m8n8.x4.shared.b16 {%0,%1,%2,%3}, [%4];"
        : "=r"(r[0]), "=r"(r[1]), "=r"(r[2]), "=r"(r[3]) : "r"(a));
}
__device__ __forceinline__ void ldsm4t(uint32_t* r, uint32_t a) {
    asm volatile("ldmatrix.sync.aligned.m8n8.x4.trans.shared.b16 {%0,%1,%2,%3}, [%4];"
        : "=r"(r[0]), "=r"(r[1]), "=r"(r[2]), "=r"(r[3]) : "r"(a));
}
__device__ __forceinline__ void mma16816(float* d, const uint32_t* a, uint32_t b0, uint32_t b1) {
    asm volatile("mma.sync.aligned.m16n8k16.row.col.f32.f16.f16.f32 "
        "{%0,%1,%2,%3}, {%4,%5,%6,%7}, {%8,%9}, {%0,%1,%2,%3};"
        : "+f"(d[0]), "+f"(d[1]), "+f"(d[2]), "+f"(d[3])
        : "r"(a[0]), "r"(a[1]), "r"(a[2]), "r"(a[3]), "r"(b0), "r"(b1));
}
// pack two f32 -> half2, then ex2 on both halves in ONE MUFU op
__device__ __forceinline__ uint32_t ex2p(float a, float b) {
    __half2 h = __floats2half2_rn(a, b);
    uint32_t x = *(uint32_t*)&h, r;
    asm("ex2.approx.f16x2 %0, %1;" : "=r"(r) : "r"(x));
    return r;
}

#define ONE2 0x3C003C00u   // half2 {1.0, 1.0}

// -------- kernel 1: Q (fp16, x log2e), K (fp16), V (fp16), norms, block max --------
__global__ void __launch_bounds__(128) qv_kernel(
    const float* __restrict__ inp, const float* __restrict__ W1,
    const float* __restrict__ b1,  const float* __restrict__ W2,
    const float* __restrict__ b2)
{
    __shared__ float Xs[32][32];
    __shared__ float W1s[16][32];
    __shared__ float W2s[32][32];
    __shared__ float b1s[16];
    __shared__ float b2s[32];
    __shared__ float Aq[32][16];

    int b  = blockIdx.x >> 8;
    int hw = blockIdx.x & 255;
    int tid = threadIdx.x;

    const float* ib = inp + (size_t)b * 262144 + hw * 32;
    for (int idx = tid; idx < 1024; idx += 128) {
        int l = idx >> 5, c = idx & 31;
        Xs[l][c] = ib[l * 8192 + c];
    }
    for (int idx = tid; idx < 512;  idx += 128) W1s[idx >> 5][idx & 31] = W1[idx];
    for (int idx = tid; idx < 1024; idx += 128) W2s[idx >> 5][idx & 31] = W2[idx];
    if (tid < 16) b1s[tid] = b1[tid];
    if (tid >= 32 && tid < 64) b2s[tid - 32] = b2[tid - 32];
    __syncthreads();

    for (int idx = tid; idx < 1024; idx += 128) {
        int o = idx >> 5, c = idx & 31;
        float s = b2s[o];
        #pragma unroll
        for (int l = 0; l < 32; l++) s += W2s[o][l] * Xs[l][c];
        g_Vh[b][o * 256 + hw][c] = __float2half(s);
    }
    for (int idx = tid; idx < 512; idx += 128) {
        int o = idx >> 5, ch = idx & 31;
        float s = b1s[o];
        #pragma unroll
        for (int l = 0; l < 32; l++) s += W1s[o][l] * Xs[l][ch];
        int k = ch >> 1, i12 = ch & 1;
        int row = i12 * 4096 + o * 256 + hw;
        g_Qh[b][row][k] = __float2half(s * L2E);
        g_Kh[b][row][k] = __float2half(s);
        Aq[(o << 1) | i12][k] = s;
    }
    __syncthreads();

    if (tid < 32) {
        int o = tid >> 1, i12 = tid & 1;
        float s = 0.f;
        #pragma unroll
        for (int k = 0; k < 16; k++) { float v = Aq[tid][k]; s += v * v; }
        g_Rn[b][i12 * 4096 + o * 256 + hw] = s;
        float m = s;
        #pragma unroll
        for (int off = 16; off; off >>= 1)
            m = fmaxf(m, __shfl_xor_sync(0xffffffffu, m, off));
        if (tid == 0) g_bmax[b][hw] = m;
    }
}

// -------- kernel 2: FA2-style fp16 mma.sync attention, fused S/exp/PV pipeline --------
__global__ void __launch_bounds__(128, 1) attn4_kernel(
    const float* __restrict__ inp, const float* __restrict__ gamma,
    float* __restrict__ out)
{
    __shared__ __align__(16) __half Qs[BM * 16];        // 2 KB
    __shared__ __align__(16) __half Ks[2][128 * 16];    // 2x4 KB
    __shared__ __align__(16) __half Vs[2][128 * 32];    // 2x8 KB
    __shared__ float red[4];

    int tid = threadIdx.x, lane = tid & 31, wid = tid >> 5;
    int b = blockIdx.y;
    int i0 = blockIdx.x * BM;
    int wrow = wid * 16;

    // ---- preload Q tile + tile-0 K/V; fold in the 256-way max reduce ----
    float mv = fmaxf(g_bmax[b][tid], g_bmax[b][tid + 128]);
    {
        int r = tid >> 1, s = tid & 1;               // Q: 128 uint4 (64 rows x 2 segs)
        ((uint4*)Qs)[r * 2 + (s ^ ((r >> 2) & 1))] = *(const uint4*)&g_Qh[b][i0 + r][s * 8];
    }
    #pragma unroll
    for (int u = 0; u < 2; u++) {                    // K: 256 uint4
        int e = tid + 128 * u;
        int r = e >> 1, s = e & 1;
        ((uint4*)Ks[0])[r * 2 + (s ^ ((r >> 2) & 1))] = *(const uint4*)&g_Kh[b][r][s * 8];
    }
    #pragma unroll
    for (int u = 0; u < 4; u++) {                    // V: 512 uint4
        int e = tid + 128 * u;
        int r = e >> 2, s = e & 3;
        ((uint4*)Vs[0])[r * 4 + (s ^ ((r >> 1) & 3))] = *(const uint4*)&g_Vh[b][r][s * 8];
    }
    #pragma unroll
    for (int off = 16; off; off >>= 1)
        mv = fmaxf(mv, __shfl_xor_sync(0xffffffffu, mv, off));
    if (lane == 0) red[wid] = mv;
    __syncthreads();

    float msq = fmaxf(fmaxf(red[0], red[1]), fmaxf(red[2], red[3]));

    // ---- Q A-fragments (once) ----
    uint32_t qa[4];
    {
        int row = wrow + (lane & 7) + (lane & 8);
        int seg = lane >> 4;
        ldsm4(qa, smem_u32(Qs) + row * 32 + (seg ^ ((row >> 2) & 1)) * 16);
    }

    int ia = i0 + wrow + (lane >> 2);
    float mh2a = L2E * sqrtf(g_Rn[b][ia] * msq);
    float mh2b = L2E * sqrtf(g_Rn[b][ia + 8] * msq);

    float Dc[16];
    #pragma unroll
    for (int t = 0; t < 16; t++) Dc[t] = 0.f;
    float Dl[4] = {0.f, 0.f, 0.f, 0.f};

    uint32_t kbase0 = smem_u32(Ks[0]), kbase1 = smem_u32(Ks[1]);
    uint32_t vbase0 = smem_u32(Vs[0]), vbase1 = smem_u32(Vs[1]);

    for (int t = 0; t < NTILES; t++) {
        uint4 kpre[2], vpre[4];
        if (t < NTILES - 1) {
            int jb2 = (t + 1) * 128;
            #pragma unroll
            for (int u = 0; u < 2; u++) {
                int e = tid + 128 * u;
                kpre[u] = *(const uint4*)&g_Kh[b][jb2 + (e >> 1)][(e & 1) * 8];
            }
            #pragma unroll
            for (int u = 0; u < 4; u++) {
                int e = tid + 128 * u;
                vpre[u] = *(const uint4*)&g_Vh[b][jb2 + (e >> 2)][(e & 3) * 8];
            }
        }

        uint32_t kb = (t & 1) ? kbase1 : kbase0;
        uint32_t vb = (t & 1) ? vbase1 : vbase0;

        // ---- fused: per 16-col strip, S-MMA -> ex2 -> Dl + PV immediately ----
        #pragma unroll
        for (int np = 0; np < 8; np++) {
            uint32_t kf[4];
            {
                int row = np * 16 + (lane & 7) + ((lane >> 4) << 3);
                int seg = (lane >> 3) & 1;
                ldsm4(kf, kb + row * 32 + (seg ^ ((row >> 2) & 1)) * 16);
            }
            uint32_t vf0[4], vf1[4];
            {
                int row = np * 16 + (lane & 7) + (((lane >> 3) & 1) << 3);
                int seg = (lane >> 4) & 1;
                ldsm4t(vf0, vb + row * 64 + ((seg)     ^ ((row >> 1) & 3)) * 16);
                ldsm4t(vf1, vb + row * 64 + ((seg + 2) ^ ((row >> 1) & 3)) * 16);
            }
            float s0[4] = {-mh2a, -mh2a, -mh2b, -mh2b};
            mma16816(s0, qa, kf[0], kf[1]);
            float s1[4] = {-mh2a, -mh2a, -mh2b, -mh2b};
            mma16816(s1, qa, kf[2], kf[3]);

            uint32_t pA[4];
            pA[0] = ex2p(s0[0], s0[1]);
            pA[1] = ex2p(s0[2], s0[3]);
            pA[2] = ex2p(s1[0], s1[1]);
            pA[3] = ex2p(s1[2], s1[3]);

            mma16816(Dl, pA, ONE2, ONE2);
            mma16816(Dc + 0,  pA, vf0[0], vf0[1]);
            mma16816(Dc + 4,  pA, vf0[2], vf0[3]);
            mma16816(Dc + 8,  pA, vf1[0], vf1[1]);
            mma16816(Dc + 12, pA, vf1[2], vf1[3]);
        }

        // ---- stage next tile into the other buffer ----
        if (t < NTILES - 1) {
            int nxt = (t + 1) & 1;
            #pragma unroll
            for (int u = 0; u < 2; u++) {
                int e = tid + 128 * u;
                int r = e >> 1, s = e & 1;
                ((uint4*)Ks[nxt])[r * 2 + (s ^ ((r >> 2) & 1))] = kpre[u];
            }
            #pragma unroll
            for (int u = 0; u < 4; u++) {
                int e = tid + 128 * u;
                int r = e >> 2, s = e & 3;
                ((uint4*)Vs[nxt])[r * 4 + (s ^ ((r >> 1) & 3))] = vpre[u];
            }
        }
        __syncthreads();
    }

    // ---- normalize, residual, write ----
    float g = gamma[0];
    float ra = g / Dl[0], rb = g / Dl[2];
    size_t ba = (size_t)b * 262144 + (size_t)ia * 32;
    size_t bb = ba + 8 * 32;
    #pragma unroll
    for (int nt = 0; nt < 4; nt++) {
        int col = nt * 8 + (lane & 3) * 2;
        float2 iv = *(const float2*)(inp + ba + col);
        float2 ov;
        ov.x = Dc[nt * 4 + 0] * ra + iv.x;
        ov.y = Dc[nt * 4 + 1] * ra + iv.y;
        *(float2*)(out + ba + col) = ov;
        iv = *(const float2*)(inp + bb + col);
        ov.x = Dc[nt * 4 + 2] * rb + iv.x;
        ov.y = Dc[nt * 4 + 3] * rb + iv.y;
        *(float2*)(out + bb + col) = ov;
    }
}

extern "C" void kernel_launch(void* const* d_in, const int* in_sizes, int n_in,
                              void* d_out, int out_size) {
    const float* inp   = (const float*)d_in[0];
    const float* W1    = (const float*)d_in[1];
    const float* b1    = (const float*)d_in[2];
    const float* W2    = (const float*)d_in[3];
    const float* b2    = (const float*)d_in[4];
    const float* gamma = (const float*)d_in[5];
    float* out = (float*)d_out;

    qv_kernel<<<NB * 256, 128>>>(inp, W1, b1, W2, b2);
    attn4_kernel<<<dim3(NN / BM, NB), 128>>>(inp, gamma, out);
}

// round 7
// speedup vs baseline: 1.0975x; 1.0975x over previous
#include <cuda_runtime.h>
#include <cuda_fp16.h>
#include <cstdint>

#define NB 2
#define NN 8192
#define BM 64
#define NTILES 64
#define L2E 1.4426950408889634f

// -------- scratch (device globals; no allocation allowed) --------
__device__ __align__(16) __half g_Qh[NB][NN][16];  // fp16 Q, pre-scaled by log2e (A side)
__device__ __align__(16) __half g_Kh[NB][NN][16];  // fp16 K, unscaled (B side)
__device__ __align__(16) __half g_Vh[NB][NN][32];  // fp16 V
__device__ float g_Rn[NB][NN];                     // |Q_i|^2 (fp32, unscaled)
__device__ float g_bmax[NB][256];                  // per-block max |Q|^2 (no reset needed)

// ---------------- helpers ----------------
__device__ __forceinline__ uint32_t smem_u32(const void* p) {
    uint32_t a;
    asm("{ .reg .u64 t; cvta.to.shared.u64 t, %1; cvt.u32.u64 %0, t; }" : "=r"(a) : "l"(p));
    return a;
}
__device__ __forceinline__ void ldsm4(uint32_t* r, uint32_t a) {
    asm volatile("ldmatrix.sync.aligned.m8n8.x4.shared.b16 {%0,%1,%2,%3}, [%4];"
        : "=r"(r[0]), "=r"(r[1]), "=r"(r[2]), "=r"(r[3]) : "r"(a));
}
__device__ __forceinline__ void ldsm4t(uint32_t* r, uint32_t a) {
    asm volatile("ldmatrix.sync.aligned.m8n8.x4.trans.shared.b16 {%0,%1,%2,%3}, [%4];"
        : "=r"(r[0]), "=r"(r[1]), "=r"(r[2]), "=r"(r[3]) : "r"(a));
}
__device__ __forceinline__ void mma16816(float* d, const uint32_t* a, uint32_t b0, uint32_t b1) {
    asm volatile("mma.sync.aligned.m16n8k16.row.col.f32.f16.f16.f32 "
        "{%0,%1,%2,%3}, {%4,%5,%6,%7}, {%8,%9}, {%0,%1,%2,%3};"
        : "+f"(d[0]), "+f"(d[1]), "+f"(d[2]), "+f"(d[3])
        : "r"(a[0]), "r"(a[1]), "r"(a[2]), "r"(a[3]), "r"(b0), "r"(b1));
}
__device__ __forceinline__ uint32_t ex2p(float a, float b) {
    __half2 h = __floats2half2_rn(a, b);
    uint32_t x = *(uint32_t*)&h, r;
    asm("ex2.approx.f16x2 %0, %1;" : "=r"(r) : "r"(x));
    return r;
}
__device__ __forceinline__ void cp16(uint32_t dst, const void* src) {
    asm volatile("cp.async.ca.shared.global [%0], [%1], 16;" :: "r"(dst), "l"(src));
}
#define CP_COMMIT() asm volatile("cp.async.commit_group;" ::: "memory")
#define CP_WAIT1()  asm volatile("cp.async.wait_group 1;" ::: "memory")
#define CP_WAIT0()  asm volatile("cp.async.wait_group 0;" ::: "memory")

#define ONE2 0x3C003C00u   // half2 {1.0, 1.0}

// -------- kernel 1: Q (fp16, x log2e), K (fp16), V (fp16), norms, block max --------
__global__ void __launch_bounds__(128) qv_kernel(
    const float* __restrict__ inp, const float* __restrict__ W1,
    const float* __restrict__ b1,  const float* __restrict__ W2,
    const float* __restrict__ b2)
{
    __shared__ float Xs[32][32];
    __shared__ float W1s[16][32];
    __shared__ float W2s[32][32];
    __shared__ float b1s[16];
    __shared__ float b2s[32];
    __shared__ float Aq[32][16];

    int b  = blockIdx.x >> 8;
    int hw = blockIdx.x & 255;
    int tid = threadIdx.x;

    const float* ib = inp + (size_t)b * 262144 + hw * 32;
    for (int idx = tid; idx < 1024; idx += 128) {
        int l = idx >> 5, c = idx & 31;
        Xs[l][c] = ib[l * 8192 + c];
    }
    for (int idx = tid; idx < 512;  idx += 128) W1s[idx >> 5][idx & 31] = W1[idx];
    for (int idx = tid; idx < 1024; idx += 128) W2s[idx >> 5][idx & 31] = W2[idx];
    if (tid < 16) b1s[tid] = b1[tid];
    if (tid >= 32 && tid < 64) b2s[tid - 32] = b2[tid - 32];
    __syncthreads();

    for (int idx = tid; idx < 1024; idx += 128) {
        int o = idx >> 5, c = idx & 31;
        float s = b2s[o];
        #pragma unroll
        for (int l = 0; l < 32; l++) s += W2s[o][l] * Xs[l][c];
        g_Vh[b][o * 256 + hw][c] = __float2half(s);
    }
    for (int idx = tid; idx < 512; idx += 128) {
        int o = idx >> 5, ch = idx & 31;
        float s = b1s[o];
        #pragma unroll
        for (int l = 0; l < 32; l++) s += W1s[o][l] * Xs[l][ch];
        int k = ch >> 1, i12 = ch & 1;
        int row = i12 * 4096 + o * 256 + hw;
        g_Qh[b][row][k] = __float2half(s * L2E);
        g_Kh[b][row][k] = __float2half(s);
        Aq[(o << 1) | i12][k] = s;
    }
    __syncthreads();

    if (tid < 32) {
        int o = tid >> 1, i12 = tid & 1;
        float s = 0.f;
        #pragma unroll
        for (int k = 0; k < 16; k++) { float v = Aq[tid][k]; s += v * v; }
        g_Rn[b][i12 * 4096 + o * 256 + hw] = s;
        float m = s;
        #pragma unroll
        for (int off = 16; off; off >>= 1)
            m = fmaxf(m, __shfl_xor_sync(0xffffffffu, m, off));
        if (tid == 0) g_bmax[b][hw] = m;
    }
}

// -------- kernel 2: fp16 mma.sync attention, j split across 2 warp-groups --------
// warp (strip = wid&3, group = wid>>2): rows strip*16, j-cols group*64..+64 of every tile.
// Fixed-shift softmax => the two groups' (D, l) partials add at the end.
__global__ void __launch_bounds__(256, 2) attn5_kernel(
    const float* __restrict__ inp, const float* __restrict__ gamma,
    float* __restrict__ out)
{
    __shared__ __align__(16) __half Qs[BM * 16];        // 2 KB
    __shared__ __align__(16) __half Ks[2][128 * 16];    // 2x4 KB
    __shared__ __align__(16) __half Vs[2][128 * 32];    // 2x8 KB
    __shared__ float red[8];

    int tid = threadIdx.x, lane = tid & 31, wid = tid >> 5;
    int strip = wid & 3, group = wid >> 2;
    int b = blockIdx.y;
    int i0 = blockIdx.x * BM;

    // ---- stage tile 0/1 via cp.async; preload Q; 256-way max reduce ----
    float mv = g_bmax[b][tid];
    {
        // K tile t -> Ks[t]: 256 segs, 1/thread
        int r = tid >> 1, s = tid & 1;
        uint32_t koff = r * 32 + (s ^ ((r >> 2) & 1)) * 16;
        cp16(smem_u32(Ks[0]) + koff, &g_Kh[b][r][s * 8]);
        // V tile t -> Vs[t]: 512 segs, 2/thread
        #pragma unroll
        for (int u = 0; u < 2; u++) {
            int e = tid + 256 * u;
            int vr = e >> 2, vsg = e & 3;
            uint32_t voff = vr * 64 + (vsg ^ ((vr >> 1) & 3)) * 16;
            cp16(smem_u32(Vs[0]) + voff, &g_Vh[b][vr][vsg * 8]);
        }
        CP_COMMIT();
        cp16(smem_u32(Ks[1]) + koff, &g_Kh[b][128 + r][s * 8]);
        #pragma unroll
        for (int u = 0; u < 2; u++) {
            int e = tid + 256 * u;
            int vr = e >> 2, vsg = e & 3;
            uint32_t voff = vr * 64 + (vsg ^ ((vr >> 1) & 3)) * 16;
            cp16(smem_u32(Vs[1]) + voff, &g_Vh[b][128 + vr][vsg * 8]);
        }
        CP_COMMIT();
    }
    if (tid < 128) {   // Q: 64 rows x 2 segs
        int r = tid >> 1, s = tid & 1;
        ((uint4*)Qs)[r * 2 + (s ^ ((r >> 2) & 1))] = *(const uint4*)&g_Qh[b][i0 + r][s * 8];
    }
    #pragma unroll
    for (int off = 16; off; off >>= 1)
        mv = fmaxf(mv, __shfl_xor_sync(0xffffffffu, mv, off));
    if (lane == 0) red[wid] = mv;
    __syncthreads();

    float msq = red[0];
    #pragma unroll
    for (int w = 1; w < 8; w++) msq = fmaxf(msq, red[w]);

    // ---- Q A-fragments (once) ----
    uint32_t qa[4];
    {
        int row = strip * 16 + (lane & 7) + (lane & 8);
        int seg = lane >> 4;
        ldsm4(qa, smem_u32(Qs) + row * 32 + (seg ^ ((row >> 2) & 1)) * 16);
    }

    int ia = i0 + strip * 16 + (lane >> 2);
    float mh2a = L2E * sqrtf(g_Rn[b][ia] * msq);
    float mh2b = L2E * sqrtf(g_Rn[b][ia + 8] * msq);

    float Dc[16];
    #pragma unroll
    for (int t = 0; t < 16; t++) Dc[t] = 0.f;
    float Dl[4] = {0.f, 0.f, 0.f, 0.f};

    uint32_t kbase0 = smem_u32(Ks[0]), kbase1 = smem_u32(Ks[1]);
    uint32_t vbase0 = smem_u32(Vs[0]), vbase1 = smem_u32(Vs[1]);

    for (int t = 0; t < NTILES; t++) {
        if (t < NTILES - 1) CP_WAIT1(); else CP_WAIT0();
        __syncthreads();

        uint32_t kb = (t & 1) ? kbase1 : kbase0;
        uint32_t vb = (t & 1) ? vbase1 : vbase0;

        // this warp's 4 strips of 16 j within the tile
        #pragma unroll
        for (int np = 0; np < 4; np++) {
            int npg = group * 4 + np;
            uint32_t kf[4];
            {
                int row = npg * 16 + (lane & 7) + ((lane >> 4) << 3);
                int seg = (lane >> 3) & 1;
                ldsm4(kf, kb + row * 32 + (seg ^ ((row >> 2) & 1)) * 16);
            }
            uint32_t vf0[4], vf1[4];
            {
                int row = npg * 16 + (lane & 7) + (((lane >> 3) & 1) << 3);
                int seg = (lane >> 4) & 1;
                ldsm4t(vf0, vb + row * 64 + ((seg)     ^ ((row >> 1) & 3)) * 16);
                ldsm4t(vf1, vb + row * 64 + ((seg + 2) ^ ((row >> 1) & 3)) * 16);
            }
            float s0[4] = {-mh2a, -mh2a, -mh2b, -mh2b};
            mma16816(s0, qa, kf[0], kf[1]);
            float s1[4] = {-mh2a, -mh2a, -mh2b, -mh2b};
            mma16816(s1, qa, kf[2], kf[3]);

            uint32_t pA[4];
            pA[0] = ex2p(s0[0], s0[1]);
            pA[1] = ex2p(s0[2], s0[3]);
            pA[2] = ex2p(s1[0], s1[1]);
            pA[3] = ex2p(s1[2], s1[3]);

            mma16816(Dl, pA, ONE2, ONE2);
            mma16816(Dc + 0,  pA, vf0[0], vf0[1]);
            mma16816(Dc + 4,  pA, vf0[2], vf0[3]);
            mma16816(Dc + 8,  pA, vf1[0], vf1[1]);
            mma16816(Dc + 12, pA, vf1[2], vf1[3]);
        }
        __syncthreads();

        // ---- stage tile t+2 into the buffer just freed ----
        if (t < NTILES - 2) {
            int jb2 = (t + 2) * 128;
            uint32_t kdst = (t & 1) ? kbase1 : kbase0;
            uint32_t vdst = (t & 1) ? vbase1 : vbase0;
            int r = tid >> 1, s = tid & 1;
            cp16(kdst + r * 32 + (s ^ ((r >> 2) & 1)) * 16, &g_Kh[b][jb2 + r][s * 8]);
            #pragma unroll
            for (int u = 0; u < 2; u++) {
                int e = tid + 256 * u;
                int vr = e >> 2, vsg = e & 3;
                cp16(vdst + vr * 64 + (vsg ^ ((vr >> 1) & 3)) * 16, &g_Vh[b][jb2 + vr][vsg * 8]);
            }
            CP_COMMIT();
        }
    }

    // ---- combine the two groups' partials through smem (reuse V buffers) ----
    float* scr = (float*)Vs;   // 10 KB needed, 16 KB available
    if (group == 1) {
        float* p = scr + (strip * 32 + lane) * 20;
        #pragma unroll
        for (int q = 0; q < 16; q++) p[q] = Dc[q];
        p[16] = Dl[0];
        p[17] = Dl[2];
    }
    __syncthreads();

    if (group == 0) {
        const float* p = scr + (strip * 32 + lane) * 20;
        #pragma unroll
        for (int q = 0; q < 16; q++) Dc[q] += p[q];
        float la = Dl[0] + p[16];
        float lb = Dl[2] + p[17];

        float g = gamma[0];
        float ra = g / la, rb = g / lb;
        size_t ba = (size_t)b * 262144 + (size_t)ia * 32;
        size_t bb = ba + 8 * 32;
        #pragma unroll
        for (int nt = 0; nt < 4; nt++) {
            int col = nt * 8 + (lane & 3) * 2;
            float2 iv = *(const float2*)(inp + ba + col);
            float2 ov;
            ov.x = Dc[nt * 4 + 0] * ra + iv.x;
            ov.y = Dc[nt * 4 + 1] * ra + iv.y;
            *(float2*)(out + ba + col) = ov;
            iv = *(const float2*)(inp + bb + col);
            ov.x = Dc[nt * 4 + 2] * rb + iv.x;
            ov.y = Dc[nt * 4 + 3] * rb + iv.y;
            *(float2*)(out + bb + col) = ov;
        }
    }
}

extern "C" void kernel_launch(void* const* d_in, const int* in_sizes, int n_in,
                              void* d_out, int out_size) {
    const float* inp   = (const float*)d_in[0];
    const float* W1    = (const float*)d_in[1];
    const float* b1    = (const float*)d_in[2];
    const float* W2    = (const float*)d_in[3];
    const float* b2    = (const float*)d_in[4];
    const float* gamma = (const float*)d_in[5];
    float* out = (float*)d_out;

    qv_kernel<<<NB * 256, 128>>>(inp, W1, b1, W2, b2);
    attn5_kernel<<<dim3(NN / BM, NB), 256>>>(inp, gamma, out);
}

// round 8
// speedup vs baseline: 1.1018x; 1.0039x over previous
#include <cuda_runtime.h>
#include <cuda_fp16.h>
#include <cstdint>

#define NB 2
#define NN 8192
#define BM 64
#define NTILES 64
#define L2E 1.4426950408889634f

// -------- scratch (device globals; no allocation allowed) --------
__device__ __align__(16) __half g_Qh[NB][NN][16];  // fp16 Q, pre-scaled by log2e (A side)
__device__ __align__(16) __half g_Kh[NB][NN][16];  // fp16 K, unscaled (B side)
__device__ __align__(16) __half g_Vh[NB][NN][32];  // fp16 V
__device__ float g_Rn[NB][NN];                     // |Q_i|^2 (fp32, unscaled)
__device__ float g_bmax[NB][256];                  // per-block max |Q|^2 (no reset needed)

// ---------------- helpers ----------------
__device__ __forceinline__ uint32_t smem_u32(const void* p) {
    uint32_t a;
    asm("{ .reg .u64 t; cvta.to.shared.u64 t, %1; cvt.u32.u64 %0, t; }" : "=r"(a) : "l"(p));
    return a;
}
__device__ __forceinline__ void ldsm4(uint32_t* r, uint32_t a) {
    asm volatile("ldmatrix.sync.aligned.m8n8.x4.shared.b16 {%0,%1,%2,%3}, [%4];"
        : "=r"(r[0]), "=r"(r[1]), "=r"(r[2]), "=r"(r[3]) : "r"(a));
}
__device__ __forceinline__ void ldsm4t(uint32_t* r, uint32_t a) {
    asm volatile("ldmatrix.sync.aligned.m8n8.x4.trans.shared.b16 {%0,%1,%2,%3}, [%4];"
        : "=r"(r[0]), "=r"(r[1]), "=r"(r[2]), "=r"(r[3]) : "r"(a));
}
__device__ __forceinline__ void mma16816(float* d, const uint32_t* a, uint32_t b0, uint32_t b1) {
    asm volatile("mma.sync.aligned.m16n8k16.row.col.f32.f16.f16.f32 "
        "{%0,%1,%2,%3}, {%4,%5,%6,%7}, {%8,%9}, {%0,%1,%2,%3};"
        : "+f"(d[0]), "+f"(d[1]), "+f"(d[2]), "+f"(d[3])
        : "r"(a[0]), "r"(a[1]), "r"(a[2]), "r"(a[3]), "r"(b0), "r"(b1));
}
__device__ __forceinline__ uint32_t ex2p(float a, float b) {
    __half2 h = __floats2half2_rn(a, b);
    uint32_t x = *(uint32_t*)&h, r;
    asm("ex2.approx.f16x2 %0, %1;" : "=r"(r) : "r"(x));
    return r;
}
__device__ __forceinline__ void cp16(uint32_t dst, const void* src) {
    asm volatile("cp.async.ca.shared.global [%0], [%1], 16;" :: "r"(dst), "l"(src));
}
#define CP_COMMIT() asm volatile("cp.async.commit_group;" ::: "memory")
#define CP_WAIT1()  asm volatile("cp.async.wait_group 1;" ::: "memory")
#define CP_WAIT0()  asm volatile("cp.async.wait_group 0;" ::: "memory")

#define ONE2 0x3C003C00u   // half2 {1.0, 1.0}

// -------- kernel 1: Q (fp16, x log2e), K (fp16), V (fp16), norms, block max --------
__global__ void __launch_bounds__(128) qv_kernel(
    const float* __restrict__ inp, const float* __restrict__ W1,
    const float* __restrict__ b1,  const float* __restrict__ W2,
    const float* __restrict__ b2)
{
    __shared__ float Xs[32][32];
    __shared__ float W1s[16][32];
    __shared__ float W2s[32][32];
    __shared__ float b1s[16];
    __shared__ float b2s[32];
    __shared__ float Aq[32][16];

    int b  = blockIdx.x >> 8;
    int hw = blockIdx.x & 255;
    int tid = threadIdx.x;

    const float* ib = inp + (size_t)b * 262144 + hw * 32;
    for (int idx = tid; idx < 1024; idx += 128) {
        int l = idx >> 5, c = idx & 31;
        Xs[l][c] = ib[l * 8192 + c];
    }
    for (int idx = tid; idx < 512;  idx += 128) W1s[idx >> 5][idx & 31] = W1[idx];
    for (int idx = tid; idx < 1024; idx += 128) W2s[idx >> 5][idx & 31] = W2[idx];
    if (tid < 16) b1s[tid] = b1[tid];
    if (tid >= 32 && tid < 64) b2s[tid - 32] = b2[tid - 32];
    __syncthreads();

    for (int idx = tid; idx < 1024; idx += 128) {
        int o = idx >> 5, c = idx & 31;
        float s = b2s[o];
        #pragma unroll
        for (int l = 0; l < 32; l++) s += W2s[o][l] * Xs[l][c];
        g_Vh[b][o * 256 + hw][c] = __float2half(s);
    }
    for (int idx = tid; idx < 512; idx += 128) {
        int o = idx >> 5, ch = idx & 31;
        float s = b1s[o];
        #pragma unroll
        for (int l = 0; l < 32; l++) s += W1s[o][l] * Xs[l][ch];
        int k = ch >> 1, i12 = ch & 1;
        int row = i12 * 4096 + o * 256 + hw;
        g_Qh[b][row][k] = __float2half(s * L2E);
        g_Kh[b][row][k] = __float2half(s);
        Aq[(o << 1) | i12][k] = s;
    }
    __syncthreads();

    if (tid < 32) {
        int o = tid >> 1, i12 = tid & 1;
        float s = 0.f;
        #pragma unroll
        for (int k = 0; k < 16; k++) { float v = Aq[tid][k]; s += v * v; }
        g_Rn[b][i12 * 4096 + o * 256 + hw] = s;
        float m = s;
        #pragma unroll
        for (int off = 16; off; off >>= 1)
            m = fmaxf(m, __shfl_xor_sync(0xffffffffu, m, off));
        if (tid == 0) g_bmax[b][hw] = m;
    }
}

// ---- smem layout (one static arena, manually carved) ----
#define SQ_OFF   0            // Q: 2 KB
#define SK_OFF   2048         // K: 3 x 4 KB
#define SV_OFF   14336        // V: 3 x 8 KB
#define SRED_OFF 38912        // 8 floats
#define SM_BYTES 38944
// combine scratch overlays [0, 28416) after the mainloop

// -------- kernel 2: fp16 mma.sync attention; warps = 2 row-halves x 4 j-groups --------
// warp w: rows (w&1)*32..+32, j-cols (w>>1)*32..+32 of every 128-j tile.
// Fixed-shift softmax => the 4 j-groups' (D, l) partials add exactly at the end.
__global__ void __launch_bounds__(256, 2) attn6_kernel(
    const float* __restrict__ inp, const float* __restrict__ gamma,
    float* __restrict__ out)
{
    __shared__ __align__(16) char sm[SM_BYTES];

    int tid = threadIdx.x, lane = tid & 31, wid = tid >> 5;
    int rh = wid & 1, g = wid >> 1;
    int b = blockIdx.y;
    int i0 = blockIdx.x * BM;

    uint32_t sb = smem_u32(sm);
    float* red = (float*)(sm + SRED_OFF);

    // ---- stage tiles 0/1 via cp.async; load Q; 256-way max reduce ----
    float mv = g_bmax[b][tid];
    {
        int r = tid >> 1, s = tid & 1;
        uint32_t koff = r * 32 + (s ^ ((r >> 2) & 1)) * 16;
        int vr0 = tid >> 2, vs0 = tid & 3;
        int e1 = tid + 256, vr1 = e1 >> 2, vs1 = e1 & 3;
        uint32_t voff0 = vr0 * 64 + (vs0 ^ ((vr0 >> 1) & 3)) * 16;
        uint32_t voff1 = vr1 * 64 + (vs1 ^ ((vr1 >> 1) & 3)) * 16;

        cp16(sb + SK_OFF + koff, &g_Kh[b][r][s * 8]);
        cp16(sb + SV_OFF + voff0, &g_Vh[b][vr0][vs0 * 8]);
        cp16(sb + SV_OFF + voff1, &g_Vh[b][vr1][vs1 * 8]);
        CP_COMMIT();
        cp16(sb + SK_OFF + 4096 + koff, &g_Kh[b][128 + r][s * 8]);
        cp16(sb + SV_OFF + 8192 + voff0, &g_Vh[b][128 + vr0][vs0 * 8]);
        cp16(sb + SV_OFF + 8192 + voff1, &g_Vh[b][128 + vr1][vs1 * 8]);
        CP_COMMIT();
    }
    if (tid < 128) {   // Q: 64 rows x 2 segs
        int r = tid >> 1, s = tid & 1;
        ((uint4*)(sm + SQ_OFF))[r * 2 + (s ^ ((r >> 2) & 1))] =
            *(const uint4*)&g_Qh[b][i0 + r][s * 8];
    }
    #pragma unroll
    for (int off = 16; off; off >>= 1)
        mv = fmaxf(mv, __shfl_xor_sync(0xffffffffu, mv, off));
    if (lane == 0) red[wid] = mv;
    __syncthreads();

    float msq = red[0];
    #pragma unroll
    for (int w = 1; w < 8; w++) msq = fmaxf(msq, red[w]);

    // ---- Q A-fragments: 2 per warp (rows rh*32 + fr*16) ----
    uint32_t qa[2][4];
    #pragma unroll
    for (int fr = 0; fr < 2; fr++) {
        int row = rh * 32 + fr * 16 + (lane & 7) + (lane & 8);
        int seg = lane >> 4;
        ldsm4(qa[fr], sb + SQ_OFF + row * 32 + (seg ^ ((row >> 2) & 1)) * 16);
    }

    float mh[2][2];
    int iab[2];
    #pragma unroll
    for (int fr = 0; fr < 2; fr++) {
        int ia = i0 + rh * 32 + fr * 16 + (lane >> 2);
        iab[fr] = ia;
        mh[fr][0] = L2E * sqrtf(g_Rn[b][ia] * msq);
        mh[fr][1] = L2E * sqrtf(g_Rn[b][ia + 8] * msq);
    }

    float Dc[2][16];
    float Dl[2][4];
    #pragma unroll
    for (int fr = 0; fr < 2; fr++) {
        #pragma unroll
        for (int q = 0; q < 16; q++) Dc[fr][q] = 0.f;
        #pragma unroll
        for (int q = 0; q < 4; q++) Dl[fr][q] = 0.f;
    }

    int cur = 0;   // buffer index of tile t
    for (int t = 0; t < NTILES; t++) {
        if (t < NTILES - 1) CP_WAIT1(); else CP_WAIT0();
        __syncthreads();

        // stage tile t+2 into the buffer freed at t-1
        if (t < NTILES - 2) {
            int nxt2 = cur + 2; if (nxt2 >= 3) nxt2 -= 3;
            int jb2 = (t + 2) * 128;
            int r = tid >> 1, s = tid & 1;
            cp16(sb + SK_OFF + nxt2 * 4096 + r * 32 + (s ^ ((r >> 2) & 1)) * 16,
                 &g_Kh[b][jb2 + r][s * 8]);
            int vr0 = tid >> 2, vs0 = tid & 3;
            int e1 = tid + 256, vr1 = e1 >> 2, vs1 = e1 & 3;
            cp16(sb + SV_OFF + nxt2 * 8192 + vr0 * 64 + (vs0 ^ ((vr0 >> 1) & 3)) * 16,
                 &g_Vh[b][jb2 + vr0][vs0 * 8]);
            cp16(sb + SV_OFF + nxt2 * 8192 + vr1 * 64 + (vs1 ^ ((vr1 >> 1) & 3)) * 16,
                 &g_Vh[b][jb2 + vr1][vs1 * 8]);
            CP_COMMIT();
        }

        uint32_t kb = sb + SK_OFF + cur * 4096;
        uint32_t vb = sb + SV_OFF + cur * 8192;

        // this warp's 2 strips of 16 j within its 32-col group
        #pragma unroll
        for (int np = 0; np < 2; np++) {
            int npg = g * 2 + np;
            uint32_t kf[4];
            {
                int row = npg * 16 + (lane & 7) + ((lane >> 4) << 3);
                int seg = (lane >> 3) & 1;
                ldsm4(kf, kb + row * 32 + (seg ^ ((row >> 2) & 1)) * 16);
            }
            uint32_t vf0[4], vf1[4];
            {
                int row = npg * 16 + (lane & 7) + (((lane >> 3) & 1) << 3);
                int seg = (lane >> 4) & 1;
                ldsm4t(vf0, vb + row * 64 + ((seg)     ^ ((row >> 1) & 3)) * 16);
                ldsm4t(vf1, vb + row * 64 + ((seg + 2) ^ ((row >> 1) & 3)) * 16);
            }
            #pragma unroll
            for (int fr = 0; fr < 2; fr++) {
                float s0[4] = {-mh[fr][0], -mh[fr][0], -mh[fr][1], -mh[fr][1]};
                mma16816(s0, qa[fr], kf[0], kf[1]);
                float s1[4] = {-mh[fr][0], -mh[fr][0], -mh[fr][1], -mh[fr][1]};
                mma16816(s1, qa[fr], kf[2], kf[3]);

                uint32_t pA[4];
                pA[0] = ex2p(s0[0], s0[1]);
                pA[1] = ex2p(s0[2], s0[3]);
                pA[2] = ex2p(s1[0], s1[1]);
                pA[3] = ex2p(s1[2], s1[3]);

                mma16816(Dl[fr], pA, ONE2, ONE2);
                mma16816(Dc[fr] + 0,  pA, vf0[0], vf0[1]);
                mma16816(Dc[fr] + 4,  pA, vf0[2], vf0[3]);
                mma16816(Dc[fr] + 8,  pA, vf1[0], vf1[1]);
                mma16816(Dc[fr] + 12, pA, vf1[2], vf1[3]);
            }
        }
        cur++; if (cur == 3) cur = 0;
    }

    // ---- combine the 4 j-groups' partials (scratch overlays K/V region) ----
    __syncthreads();   // everyone done reading tile buffers
    float* scr = (float*)sm;
    if (g > 0) {
        float* p = scr + (((g - 1) * 2 + rh) * 32 + lane) * 37;
        #pragma unroll
        for (int fr = 0; fr < 2; fr++) {
            #pragma unroll
            for (int q = 0; q < 16; q++) p[fr * 16 + q] = Dc[fr][q];
        }
        p[32] = Dl[0][0]; p[33] = Dl[0][2];
        p[34] = Dl[1][0]; p[35] = Dl[1][2];
    }
    __syncthreads();

    if (g == 0) {
        float la[2], lb[2];
        la[0] = Dl[0][0]; lb[0] = Dl[0][2];
        la[1] = Dl[1][0]; lb[1] = Dl[1][2];
        #pragma unroll
        for (int gg = 0; gg < 3; gg++) {
            const float* p = scr + ((gg * 2 + rh) * 32 + lane) * 37;
            #pragma unroll
            for (int fr = 0; fr < 2; fr++) {
                #pragma unroll
                for (int q = 0; q < 16; q++) Dc[fr][q] += p[fr * 16 + q];
            }
            la[0] += p[32]; lb[0] += p[33];
            la[1] += p[34]; lb[1] += p[35];
        }

        float gm = gamma[0];
        #pragma unroll
        for (int fr = 0; fr < 2; fr++) {
            float ra = gm / la[fr], rb = gm / lb[fr];
            size_t ba = (size_t)b * 262144 + (size_t)iab[fr] * 32;
            size_t bb = ba + 8 * 32;
            #pragma unroll
            for (int nt = 0; nt < 4; nt++) {
                int col = nt * 8 + (lane & 3) * 2;
                float2 iv = *(const float2*)(inp + ba + col);
                float2 ov;
                ov.x = Dc[fr][nt * 4 + 0] * ra + iv.x;
                ov.y = Dc[fr][nt * 4 + 1] * ra + iv.y;
                *(float2*)(out + ba + col) = ov;
                iv = *(const float2*)(inp + bb + col);
                ov.x = Dc[fr][nt * 4 + 2] * rb + iv.x;
                ov.y = Dc[fr][nt * 4 + 3] * rb + iv.y;
                *(float2*)(out + bb + col) = ov;
            }
        }
    }
}

extern "C" void kernel_launch(void* const* d_in, const int* in_sizes, int n_in,
                              void* d_out, int out_size) {
    const float* inp   = (const float*)d_in[0];
    const float* W1    = (const float*)d_in[1];
    const float* b1    = (const float*)d_in[2];
    const float* W2    = (const float*)d_in[3];
    const float* b2    = (const float*)d_in[4];
    const float* gamma = (const float*)d_in[5];
    float* out = (float*)d_out;

    qv_kernel<<<NB * 256, 128>>>(inp, W1, b1, W2, b2);
    attn6_kernel<<<dim3(NN / BM, NB), 256>>>(inp, gamma, out);
}